// round 15
// baseline (speedup 1.0000x reference)
#include <cuda_runtime.h>
#include <cuda_fp16.h>
#include <math.h>
#include <float.h>
#include <stdint.h>

#define HID 128
#define MAX_NODES 50000
#define MAX_EDGES 800000
#define PADN 50048   // MAX_NODES rounded to 128-row tiles

// ------------------------- scratch (static, no allocs; zero-initialized at load) -------------------------
__device__ __align__(16) __half   g_zh[PADN * HID];          // z in fp16 (padded, pad rows zeroed)
__device__ __align__(16) __half2  g_Ah[MAX_NODES * (HID/2)]; // z @ Wd (fp16)
__device__ __align__(16) __half2  g_Bh[MAX_NODES * (HID/2)]; // z @ Ws (fp16)
__device__ __align__(16) __half2  g_aggh[PADN * (HID/2)];    // agg result (fp16, pad rows zeroed)
__device__ int     g_deg[MAX_NODES];
__device__ int     g_off[MAX_NODES + 1];
__device__ int     g_cur[MAX_NODES];
__device__ int     g_csr[MAX_EDGES];

// pre-transposed fp16 weights: [n][k] layout
__device__ __align__(16) __half g_WdT[128 * 128];
__device__ __align__(16) __half g_WsT[128 * 128];
__device__ __align__(16) __half g_W1T[128 * 256];
__device__ __align__(16) __half g_W2T[128 * 128];

// ------------------------- helpers (sm_80+ baseline PTX only) -------------------------
__device__ __forceinline__ uint32_t smem_u32(const void* p) {
    uint32_t a;
    asm("{ .reg .u64 t; cvta.to.shared.u64 t, %1; cvt.u32.u64 %0, t; }" : "=r"(a) : "l"(p));
    return a;
}

__device__ __forceinline__ void cp16(uint32_t dst, const void* src) {
    asm volatile("cp.async.cg.shared.global [%0], [%1], 16;" :: "r"(dst), "l"(src));
}
#define CP_COMMIT()  asm volatile("cp.async.commit_group;" ::: "memory")
#define CP_WAIT1()   asm volatile("cp.async.wait_group 1;" ::: "memory")
#define CP_WAIT0()   asm volatile("cp.async.wait_group 0;" ::: "memory")

__device__ __forceinline__ uint32_t f2h2(float a, float b) {
    const __half2 h = __floats2half2_rn(a, b);
    return *(const uint32_t*)&h;
}

__device__ __forceinline__ void mma_f16(float* c, const uint32_t* a, uint32_t b0, uint32_t b1) {
    asm volatile(
        "mma.sync.aligned.m16n8k16.row.col.f32.f16.f16.f32 "
        "{%0,%1,%2,%3}, {%4,%5,%6,%7}, {%8,%9}, {%0,%1,%2,%3};"
        : "+f"(c[0]), "+f"(c[1]), "+f"(c[2]), "+f"(c[3])
        : "r"(a[0]), "r"(a[1]), "r"(a[2]), "r"(a[3]), "r"(b0), "r"(b1));
}

// tiling: CTA = 256 thr = 8 warps (4M x 2N), tile 128(M) x 128(N)
// pitches in half2 (uint32) units; pitch=4*odd -> frag loads conflict-free
#define PA2C 36    // chunk-A pitch (144 B/row)
#define PA2F 68    // full-A / hid pitch (272 B/row)
#define PB2  36    // B pitch, [n][k] transposed

// ------------------------- compute core: 4 k16-steps over one 64-K chunk -------------------------
__device__ __forceinline__ void mma_chunk_f16(
    float acc[2][8][4], const uint32_t* __restrict__ Asm, int apitch2, int acol2,
    const uint32_t* __restrict__ Bsm, int wm, int wn, int g, int tg)
{
#pragma unroll
    for (int kk2 = 0; kk2 < 32; kk2 += 8) {
        uint32_t a[2][4];
#pragma unroll
        for (int mt = 0; mt < 2; mt++) {
            const uint32_t* ap = Asm + (wm + mt * 16 + g) * apitch2 + acol2 + kk2 + tg;
            a[mt][0] = ap[0];
            a[mt][1] = ap[8 * apitch2];
            a[mt][2] = ap[4];
            a[mt][3] = ap[8 * apitch2 + 4];
        }
#pragma unroll
        for (int nt = 0; nt < 8; nt++) {
            const uint32_t* bp = Bsm + (wn + nt * 8 + g) * PB2 + kk2 + tg;
            const uint32_t b0 = bp[0];
            const uint32_t b1 = bp[4];
            mma_f16(acc[0][nt], a[0], b0, b1);
            mma_f16(acc[1][nt], a[1], b0, b1);
        }
    }
}

// async B fill: WT[n][kw..kw+64) fp16 -> Bs[n][k2] (row = 128B = 8x16B chunks)
__device__ __forceinline__ void cp_fill_B(
    uint32_t dstBase, const __half* __restrict__ WT, int kw, int kstride, int tid)
{
#pragma unroll
    for (int it = 0; it < 4; it++) {
        const int i = it * 256 + tid;
        const int n = i >> 3;
        const int c = i & 7;
        cp16(dstBase + n * (PB2 * 4) + c * 16, WT + (size_t)n * kstride + kw + c * 8);
    }
}

// async A chunk fill: src rows (fp16, pitch HID) -> [128][PA2C] (row = 128B = 8x16B)
__device__ __forceinline__ void cp_fill_Achunk(
    uint32_t dstBase, const __half* __restrict__ src, int tid)
{
#pragma unroll
    for (int it = 0; it < 4; it++) {
        const int i = it * 256 + tid;
        const int row = i >> 3;
        const int c = i & 7;
        cp16(dstBase + row * (PA2C * 4) + c * 16, src + (size_t)row * HID + c * 8);
    }
}

// async A full-K fill: src rows (fp16) -> [128][PA2F] (row = 256B = 16x16B)
__device__ __forceinline__ void cp_fill_Afull(
    uint32_t dstBase, const __half* __restrict__ src, int tid)
{
#pragma unroll
    for (int it = 0; it < 8; it++) {
        const int i = it * 256 + tid;
        const int row = i >> 4;
        const int c = i & 15;
        cp16(dstBase + row * (PA2F * 4) + c * 16, src + (size_t)row * HID + c * 8);
    }
}

// ------------------------- prep: weights transpose->fp16; z->fp16 (+ pad zeroing) -------------------------
__global__ void prep_weights(const float* __restrict__ Wm, const float* __restrict__ W1,
                             const float* __restrict__ W2)
{
    const int i = blockIdx.x * blockDim.x + threadIdx.x;
    if (i < 128 * 256) {
        const int n = i >> 8, k = i & 255;
        g_W1T[n * 256 + k] = __float2half_rn(W1[(size_t)k * 128 + n]);
    }
    if (i < 128 * 128) {
        const int n = i >> 7, k = i & 127;
        g_WdT[n * 128 + k] = __float2half_rn(Wm[(size_t)k * 128 + n]);
        g_WsT[n * 128 + k] = __float2half_rn(Wm[(size_t)(128 + k) * 128 + n]);
        g_W2T[n * 128 + k] = __float2half_rn(W2[(size_t)k * 128 + n]);
    }
}

__global__ void prep_z(const float* __restrict__ z, int M)
{
    const int idx = blockIdx.x * blockDim.x + threadIdx.x;  // one per 4 elements
    if (idx >= PADN * (HID / 4)) return;
    const int row = idx >> 5;
    const int c4  = (idx & 31) << 2;
    uint2 t = make_uint2(0u, 0u);
    if (row < M) {
        const float4 v = *(const float4*)(z + (size_t)row * HID + c4);
        t.x = f2h2(v.x, v.y);
        t.y = f2h2(v.z, v.w);
    }
    *(uint2*)(g_zh + (size_t)row * HID + c4) = t;
    if (row >= M)  // zero agg pad rows (agg never writes them; fused cp.async reads them)
        *(uint2*)((__half*)g_aggh + (size_t)row * HID + c4) = make_uint2(0u, 0u);
}

// ------------------------- gemm2: A tile async once; emit g_Ah = z@Wd, g_Bh = z@Ws (both fp16) -------------------------
// smem (words): As [128][PA2F] (8704) + B0 (4608) + B1 (4608) = 17920 w = 71680 B -> 2 CTA/SM
#define GEMM2_SMEM (71680)

__global__ __launch_bounds__(256, 2) void gemm2_kernel(int M)
{
    extern __shared__ uint32_t sm[];
    uint32_t* As = sm;
    uint32_t* Bb0 = sm + 128 * PA2F;
    uint32_t* Bb1 = Bb0 + 128 * PB2;
    const uint32_t aAddr = smem_u32(As);
    const uint32_t bAddr[2] = { smem_u32(Bb0), smem_u32(Bb1) };

    const int tid  = threadIdx.x;
    const int wid  = tid >> 5;
    const int lane = tid & 31;
    const int g    = lane >> 2;
    const int tg   = lane & 3;
    const int wm   = (wid & 3) << 5;
    const int wn   = (wid >> 2) << 6;
    const int rowBase = blockIdx.x * 128;

    // pipeline: group0 = B step0, group1 = A full tile
    cp_fill_B(bAddr[0], g_WdT, 0, 128, tid);
    CP_COMMIT();
    cp_fill_Afull(aAddr, g_zh + (size_t)rowBase * HID, tid);
    CP_COMMIT();

    // step table: 0:(WdT,0) 1:(WdT,64) 2:(WsT,0) 3:(WsT,64)
    for (int w = 0; w < 2; w++) {
        float acc[2][8][4];
#pragma unroll
        for (int mt = 0; mt < 2; mt++)
#pragma unroll
            for (int nt = 0; nt < 8; nt++)
#pragma unroll
                for (int i = 0; i < 4; i++) acc[mt][nt][i] = 0.f;

        for (int chunk = 0; chunk < 2; chunk++) {
            const int step = w * 2 + chunk;
            if (step < 3) {
                const __half* nWT = (step == 0) ? g_WdT : g_WsT;
                const int nkw = (step == 1) ? 0 : 64;
                cp_fill_B(bAddr[(step + 1) & 1], nWT, nkw, 128, tid);
                CP_COMMIT();
                CP_WAIT1();
            } else {
                CP_WAIT0();
            }
            __syncthreads();
            mma_chunk_f16(acc, As, PA2F, chunk * 32,
                          (step & 1) ? Bb1 : Bb0, wm, wn, g, tg);
            __syncthreads();
        }

#pragma unroll
        for (int mt = 0; mt < 2; mt++) {
            const int r0 = rowBase + wm + mt * 16 + g;
            const int r1 = r0 + 8;
#pragma unroll
            for (int nt = 0; nt < 8; nt++) {
                const int cb = wn + nt * 8 + tg * 2;
                __half2* dst = w ? g_Bh : g_Ah;
                if (r0 < M) dst[(size_t)r0 * (HID/2) + (cb >> 1)] =
                    __floats2half2_rn(acc[mt][nt][0], acc[mt][nt][1]);
                if (r1 < M) dst[(size_t)r1 * (HID/2) + (cb >> 1)] =
                    __floats2half2_rn(acc[mt][nt][2], acc[mt][nt][3]);
            }
        }
    }
}

// ------------------------- fused MLP: fully pipelined A+B; hidden = relu([z|agg]@W1+b1); out = hidden@W2+b2 -------------------------
// smem (words): A0 @0 (4608), A1 @4608, B0 @9216, B1 @13824, hid @18432 (8704) = 27136 w = 108544 B -> 2 CTA/SM
#define FUSED_SMEM (108544)

__global__ __launch_bounds__(256, 2) void fused_mlp_kernel(
    const float* __restrict__ b1, const float* __restrict__ b2,
    float* __restrict__ out, int M)
{
    extern __shared__ uint32_t sm[];
    uint32_t* Ab0 = sm;
    uint32_t* Ab1 = sm + 4608;
    uint32_t* Bb0 = sm + 9216;
    uint32_t* Bb1 = sm + 13824;
    uint32_t* hid = sm + 18432;
    const uint32_t aAddr[2] = { smem_u32(Ab0), smem_u32(Ab1) };
    const uint32_t bAddr[2] = { smem_u32(Bb0), smem_u32(Bb1) };

    const int tid  = threadIdx.x;
    const int wid  = tid >> 5;
    const int lane = tid & 31;
    const int g    = lane >> 2;
    const int tg   = lane & 3;
    const int wm   = (wid & 3) << 5;
    const int wn   = (wid >> 2) << 6;
    const int rowBase = blockIdx.x * 128;

    const __half* zbase   = g_zh + (size_t)rowBase * HID;
    const __half* aggbase = (const __half*)g_aggh + (size_t)rowBase * HID;

    // group0: A0 (z,k0) + B0 (W1T,0)
    cp_fill_Achunk(aAddr[0], zbase, tid);
    cp_fill_B(bAddr[0], g_W1T, 0, 256, tid);
    CP_COMMIT();

    float acc[2][8][4];
#pragma unroll
    for (int mt = 0; mt < 2; mt++)
#pragma unroll
        for (int nt = 0; nt < 8; nt++)
#pragma unroll
            for (int i = 0; i < 4; i++) acc[mt][nt][i] = 0.f;

    // ---- stage 1: 4 steps, K=256 over [z | agg] ----
    for (int step = 0; step < 4; step++) {
        if (step < 3) {
            const __half* asrc = (step == 0) ? zbase + 64 : aggbase + (step - 1) * 64;
            cp_fill_Achunk(aAddr[(step + 1) & 1], asrc, tid);
            cp_fill_B(bAddr[(step + 1) & 1], g_W1T, (step + 1) * 64, 256, tid);
        } else {
            cp_fill_B(bAddr[0], g_W2T, 0, 128, tid);
        }
        CP_COMMIT();
        CP_WAIT1();
        __syncthreads();
        mma_chunk_f16(acc, (step & 1) ? Ab1 : Ab0, PA2C, 0,
                      (step & 1) ? Bb1 : Bb0, wm, wn, g, tg);
        __syncthreads();
    }

    // ---- stage-1 epilogue: hid = fp16(relu(acc + b1)) ----
#pragma unroll
    for (int mt = 0; mt < 2; mt++) {
        const int lr0 = wm + mt * 16 + g;
        const int lr1 = lr0 + 8;
#pragma unroll
        for (int nt = 0; nt < 8; nt++) {
            const int cb = wn + nt * 8 + tg * 2;
            const float bb0 = b1[cb], bb1 = b1[cb + 1];
            hid[lr0 * PA2F + (cb >> 1)] =
                f2h2(fmaxf(acc[mt][nt][0] + bb0, 0.f), fmaxf(acc[mt][nt][1] + bb1, 0.f));
            hid[lr1 * PA2F + (cb >> 1)] =
                f2h2(fmaxf(acc[mt][nt][2] + bb0, 0.f), fmaxf(acc[mt][nt][3] + bb1, 0.f));
        }
    }
    __syncthreads();

    // ---- stage 2: out = hid @ W2 + b2 ----
#pragma unroll
    for (int mt = 0; mt < 2; mt++)
#pragma unroll
        for (int nt = 0; nt < 8; nt++)
#pragma unroll
            for (int i = 0; i < 4; i++) acc[mt][nt][i] = 0.f;

    cp_fill_B(bAddr[1], g_W2T, 64, 128, tid);
    CP_COMMIT();
    CP_WAIT1();                       // (W2T,0) group done
    __syncthreads();
    mma_chunk_f16(acc, hid, PA2F, 0, Bb0, wm, wn, g, tg);
    __syncthreads();
    CP_WAIT0();                       // (W2T,64) done
    __syncthreads();
    mma_chunk_f16(acc, hid, PA2F, 32, Bb1, wm, wn, g, tg);

#pragma unroll
    for (int mt = 0; mt < 2; mt++) {
        const int r0 = rowBase + wm + mt * 16 + g;
        const int r1 = r0 + 8;
#pragma unroll
        for (int nt = 0; nt < 8; nt++) {
            const int cb = wn + nt * 8 + tg * 2;
            const float bb0 = b2[cb], bb1 = b2[cb + 1];
            if (r0 < M) *(float2*)(out + (size_t)r0 * HID + cb) =
                make_float2(acc[mt][nt][0] + bb0, acc[mt][nt][1] + bb1);
            if (r1 < M) *(float2*)(out + (size_t)r1 * HID + cb) =
                make_float2(acc[mt][nt][2] + bb0, acc[mt][nt][3] + bb1);
        }
    }
}

// ------------------------- CSR build (3 kernels; zeroing folded into scan) -------------------------
__global__ void deg_kernel(const int* __restrict__ dst, int nE)
{
    int e = blockIdx.x * blockDim.x + threadIdx.x;
    if (e < nE) atomicAdd(&g_deg[dst[e]], 1);
}

__global__ __launch_bounds__(1024) void scan_kernel(int nNodes)
{
    __shared__ int warpPre[32];
    __shared__ int s_carry;
    const int tid = threadIdx.x;
    const int lane = tid & 31;
    const int wid = tid >> 5;
    if (tid == 0) s_carry = 0;
    __syncthreads();
    const int nChunks = (nNodes + 1023) >> 10;
    for (int c = 0; c < nChunks; c++) {
        const int i = (c << 10) + tid;
        const int v = (i < nNodes) ? g_deg[i] : 0;
        if (i < nNodes) g_deg[i] = 0;   // re-zero for next graph replay
        int incl = v;
#pragma unroll
        for (int o = 1; o < 32; o <<= 1) {
            int t = __shfl_up_sync(0xffffffffu, incl, o);
            if (lane >= o) incl += t;
        }
        if (lane == 31) warpPre[wid] = incl;
        __syncthreads();
        if (wid == 0) {
            int ws = warpPre[lane];
            int wincl = ws;
#pragma unroll
            for (int o = 1; o < 32; o <<= 1) {
                int t = __shfl_up_sync(0xffffffffu, wincl, o);
                if (lane >= o) wincl += t;
            }
            warpPre[lane] = wincl - ws;
        }
        __syncthreads();
        const int excl = s_carry + warpPre[wid] + incl - v;
        if (i < nNodes) { g_off[i] = excl; g_cur[i] = excl; }
        __syncthreads();
        if (tid == 1023) s_carry = excl + v;
        __syncthreads();
    }
    if (tid == 0) g_off[nNodes] = s_carry;
}

__global__ void scatter_kernel(const int* __restrict__ dst, int nE)
{
    int e = blockIdx.x * blockDim.x + threadIdx.x;
    if (e < nE) {
        int p = atomicAdd(&g_cur[dst[e]], 1);
        g_csr[p] = e;
    }
}

// ------------------------- per-node gather-max (fp16 rows, edge loop unrolled 2x) -------------------------
__global__ __launch_bounds__(256) void agg_kernel(
    const int* __restrict__ src, const float* __restrict__ ew,
    const float* __restrict__ Wm, const float* __restrict__ bm,
    int nNodes)
{
    const int warpId = (blockIdx.x * blockDim.x + threadIdx.x) >> 5;
    const int lane = threadIdx.x & 31;
    if (warpId >= nNodes) return;
    const int n = warpId;
    const float4 ww4 = *(const float4*)(Wm + 256 * HID + lane * 4);
    const int s0 = g_off[n], s1 = g_off[n + 1];
    float4 m = make_float4(-FLT_MAX, -FLT_MAX, -FLT_MAX, -FLT_MAX);
    for (int base = s0; base < s1; base += 32) {
        const int idx = base + lane;
        int sv = 0; float wv = 0.f;
        if (idx < s1) {
            const int e = g_csr[idx];
            sv = src[e];
            wv = ew[e];
        }
        const int cnt = min(32, s1 - base);
        int j = 0;
        for (; j + 1 < cnt; j += 2) {
            const int   sj0 = __shfl_sync(0xffffffffu, sv, j);
            const float wj0 = __shfl_sync(0xffffffffu, wv, j);
            const int   sj1 = __shfl_sync(0xffffffffu, sv, j + 1);
            const float wj1 = __shfl_sync(0xffffffffu, wv, j + 1);
            const uint2 h0 = *(const uint2*)(g_Bh + (size_t)sj0 * (HID/2) + lane * 2);
            const uint2 h1 = *(const uint2*)(g_Bh + (size_t)sj1 * (HID/2) + lane * 2);
            const float2 b0a = __half22float2(*(const __half2*)&h0.x);
            const float2 b0b = __half22float2(*(const __half2*)&h0.y);
            const float2 b1a = __half22float2(*(const __half2*)&h1.x);
            const float2 b1b = __half22float2(*(const __half2*)&h1.y);
            m.x = fmaxf(m.x, fmaf(wj0, ww4.x, b0a.x));
            m.y = fmaxf(m.y, fmaf(wj0, ww4.y, b0a.y));
            m.z = fmaxf(m.z, fmaf(wj0, ww4.z, b0b.x));
            m.w = fmaxf(m.w, fmaf(wj0, ww4.w, b0b.y));
            m.x = fmaxf(m.x, fmaf(wj1, ww4.x, b1a.x));
            m.y = fmaxf(m.y, fmaf(wj1, ww4.y, b1a.y));
            m.z = fmaxf(m.z, fmaf(wj1, ww4.z, b1b.x));
            m.w = fmaxf(m.w, fmaf(wj1, ww4.w, b1b.y));
        }
        if (j < cnt) {
            const int   sj = __shfl_sync(0xffffffffu, sv, j);
            const float wj = __shfl_sync(0xffffffffu, wv, j);
            const uint2 h0 = *(const uint2*)(g_Bh + (size_t)sj * (HID/2) + lane * 2);
            const float2 b0a = __half22float2(*(const __half2*)&h0.x);
            const float2 b0b = __half22float2(*(const __half2*)&h0.y);
            m.x = fmaxf(m.x, fmaf(wj, ww4.x, b0a.x));
            m.y = fmaxf(m.y, fmaf(wj, ww4.y, b0a.y));
            m.z = fmaxf(m.z, fmaf(wj, ww4.z, b0b.x));
            m.w = fmaxf(m.w, fmaf(wj, ww4.w, b0b.y));
        }
    }
    uint2 o;
    if (s1 > s0) {
        const uint2 a2 = *(const uint2*)(g_Ah + (size_t)n * (HID/2) + lane * 2);
        const float2 aa = __half22float2(*(const __half2*)&a2.x);
        const float2 ab = __half22float2(*(const __half2*)&a2.y);
        const float4 bm4 = *(const float4*)(bm + lane * 4);
        const __half2 o01 = __floats2half2_rn(aa.x + bm4.x + m.x, aa.y + bm4.y + m.y);
        const __half2 o23 = __floats2half2_rn(ab.x + bm4.z + m.z, ab.y + bm4.w + m.w);
        o.x = *(const uint32_t*)&o01;
        o.y = *(const uint32_t*)&o23;
    } else {
        o.x = 0u; o.y = 0u;
    }
    *(uint2*)(g_aggh + (size_t)n * (HID/2) + lane * 2) = o;
}

// ------------------------- launch -------------------------
extern "C" void kernel_launch(void* const* d_in, const int* in_sizes, int n_in,
                              void* d_out, int out_size)
{
    const float* z   = (const float*)d_in[0];
    const float* ew  = (const float*)d_in[1];
    const int*   esrc= (const int*)d_in[2];
    const int*   edst= (const int*)d_in[3];
    const float* Wm  = (const float*)d_in[4];
    const float* bm  = (const float*)d_in[5];
    const float* W1  = (const float*)d_in[6];
    const float* b1  = (const float*)d_in[7];
    const float* W2  = (const float*)d_in[8];
    const float* b2  = (const float*)d_in[9];
    float* out = (float*)d_out;

    const int nNodes = in_sizes[0] / HID;
    const int nEdges = in_sizes[1];

    cudaFuncSetAttribute(gemm2_kernel, cudaFuncAttributeMaxDynamicSharedMemorySize, GEMM2_SMEM);
    cudaFuncSetAttribute(fused_mlp_kernel, cudaFuncAttributeMaxDynamicSharedMemorySize, FUSED_SMEM);

    // lazily-created side stream + fork/join events (host-side objects, no device mem)
    static cudaStream_t s_side = nullptr;
    static cudaEvent_t  s_evFork = nullptr, s_evCsr = nullptr;
    if (!s_side) {
        cudaStreamCreateWithFlags(&s_side, cudaStreamNonBlocking);
        cudaEventCreateWithFlags(&s_evFork, cudaEventDisableTiming);
        cudaEventCreateWithFlags(&s_evCsr, cudaEventDisableTiming);
    }

    const int gemmGrid = (nNodes + 127) / 128;
    const int edgeGrid = (nEdges + 255) / 256;
    const int aggGrid  = (nNodes + 7) / 8;
    const int prepzGrid = (PADN * (HID / 4) + 255) / 256;

    // fork: CSR build (edge-only inputs) runs concurrently with prep + gemm2
    cudaEventRecord(s_evFork, 0);
    cudaStreamWaitEvent(s_side, s_evFork, 0);

    // side stream: CSR build (deg relies on g_deg zeroed by prior scan / static init)
    deg_kernel<<<edgeGrid, 256, 0, s_side>>>(edst, nEdges);
    scan_kernel<<<1, 1024, 0, s_side>>>(nNodes);
    scatter_kernel<<<edgeGrid, 256, 0, s_side>>>(edst, nEdges);
    cudaEventRecord(s_evCsr, s_side);

    // main stream: prep (weights fp16-T, z fp16 + pad zero), then dual projection
    prep_weights<<<128, 256>>>(Wm, W1, W2);
    prep_z<<<prepzGrid, 256>>>(z, nNodes);
    gemm2_kernel<<<gemmGrid, 256, GEMM2_SMEM>>>(nNodes);

    // join: agg needs both CSR and g_Ah/g_Bh
    cudaStreamWaitEvent(0, s_evCsr, 0);

    // segment max (gather form, fp16 rows)
    agg_kernel<<<aggGrid, 256>>>(esrc, ew, Wm, bm, nNodes);

    // fused: hidden = relu([z|agg]@W1 + b1); out = hidden@W2 + b2
    fused_mlp_kernel<<<gemmGrid, 256, FUSED_SMEM>>>(b1, b2, out, nNodes);
}

// round 16
// speedup vs baseline: 1.3153x; 1.3153x over previous
#include <cuda_runtime.h>
#include <cuda_fp16.h>
#include <math.h>
#include <float.h>
#include <stdint.h>

#define HID 128
#define MAX_NODES 50000
#define MAX_EDGES 800000

// ------------------------- scratch (static, no allocs; zero-initialized at load) -------------------------
__device__ __align__(16) __half2 g_Ah[MAX_NODES * (HID/2)]; // z @ Wd (fp16)
__device__ __align__(16) __half2 g_Bh[MAX_NODES * (HID/2)]; // z @ Ws (fp16)
__device__ __align__(16) __half2 g_aggh[MAX_NODES * (HID/2)];// agg result (fp16)
__device__ int     g_deg[MAX_NODES];
__device__ int     g_off[MAX_NODES + 1];
__device__ int     g_cur[MAX_NODES];
__device__ int     g_csr[MAX_EDGES];

// pre-transposed fp16 weights: [n][k] layout (B-tile ready)
__device__ __align__(16) __half g_WdT[128 * 128];
__device__ __align__(16) __half g_WsT[128 * 128];
__device__ __align__(16) __half g_W1T[128 * 256];
__device__ __align__(16) __half g_W2T[128 * 128];

// ------------------------- helpers (sm_80+ baseline PTX only) -------------------------
__device__ __forceinline__ uint32_t smem_u32(const void* p) {
    uint32_t a;
    asm("{ .reg .u64 t; cvta.to.shared.u64 t, %1; cvt.u32.u64 %0, t; }" : "=r"(a) : "l"(p));
    return a;
}

__device__ __forceinline__ void cp16(uint32_t dst, const void* src) {
    asm volatile("cp.async.cg.shared.global [%0], [%1], 16;" :: "r"(dst), "l"(src));
}
#define CP_COMMIT()  asm volatile("cp.async.commit_group;" ::: "memory")
#define CP_WAIT1()   asm volatile("cp.async.wait_group 1;" ::: "memory")
#define CP_WAIT0()   asm volatile("cp.async.wait_group 0;" ::: "memory")

__device__ __forceinline__ uint32_t f2h2(float a, float b) {
    const __half2 h = __floats2half2_rn(a, b);
    return *(const uint32_t*)&h;
}

__device__ __forceinline__ void mma_f16(float* c, const uint32_t* a, uint32_t b0, uint32_t b1) {
    asm volatile(
        "mma.sync.aligned.m16n8k16.row.col.f32.f16.f16.f32 "
        "{%0,%1,%2,%3}, {%4,%5,%6,%7}, {%8,%9}, {%0,%1,%2,%3};"
        : "+f"(c[0]), "+f"(c[1]), "+f"(c[2]), "+f"(c[3])
        : "r"(a[0]), "r"(a[1]), "r"(a[2]), "r"(a[3]), "r"(b0), "r"(b1));
}

// tiling: CTA = 256 thr = 8 warps (4M x 2N), tile 128(M) x 128(N)
// pitches in half2 (uint32) units; pitch=4*odd -> frag loads conflict-free
#define PA2C 36    // chunk-A pitch
#define PA2F 68    // full-A / hid pitch
#define PB2  36    // B pitch, [n][k] transposed

// ------------------------- compute core: 4 k16-steps over one 64-K chunk -------------------------
__device__ __forceinline__ void mma_chunk_f16(
    float acc[2][8][4], const uint32_t* __restrict__ Asm, int apitch2, int acol2,
    const uint32_t* __restrict__ Bsm, int wm, int wn, int g, int tg)
{
#pragma unroll
    for (int kk2 = 0; kk2 < 32; kk2 += 8) {   // 8 half2 = 16 K per step
        uint32_t a[2][4];
#pragma unroll
        for (int mt = 0; mt < 2; mt++) {
            const uint32_t* ap = Asm + (wm + mt * 16 + g) * apitch2 + acol2 + kk2 + tg;
            a[mt][0] = ap[0];
            a[mt][1] = ap[8 * apitch2];
            a[mt][2] = ap[4];
            a[mt][3] = ap[8 * apitch2 + 4];
        }
#pragma unroll
        for (int nt = 0; nt < 8; nt++) {
            const uint32_t* bp = Bsm + (wn + nt * 8 + g) * PB2 + kk2 + tg;
            const uint32_t b0 = bp[0];
            const uint32_t b1 = bp[4];
            mma_f16(acc[0][nt], a[0], b0, b1);
            mma_f16(acc[1][nt], a[1], b0, b1);
        }
    }
}

// async B fill: WT[n][kw..kw+64) fp16 -> Bs[n][k2] (row = 128B, 8x16B chunks)
__device__ __forceinline__ void cp_fill_B(
    uint32_t dstBase, const __half* __restrict__ WT, int kw, int kstride, int tid)
{
#pragma unroll
    for (int it = 0; it < 4; it++) {
        const int i = it * 256 + tid;     // 0..1023
        const int n = i >> 3;             // row 0..127
        const int c = i & 7;              // 16B chunk
        cp16(dstBase + n * (PB2 * 4) + c * 16, WT + (size_t)n * kstride + kw + c * 8);
    }
}

// ------------------------- weight prep: transpose + fp16 convert (flat, 1 elem/thread) -------------------------
__global__ void prep_weights(const float* __restrict__ Wm, const float* __restrict__ W1,
                             const float* __restrict__ W2)
{
    const int i = blockIdx.x * blockDim.x + threadIdx.x;   // 0 .. 81919
    if (i < 128 * 256) {                                    // W1T
        const int n = i >> 8, k = i & 255;
        g_W1T[n * 256 + k] = __float2half_rn(W1[(size_t)k * 128 + n]);
    } else {
        const int j = i - 128 * 256;                        // 0 .. 49151
        const int which = j >> 14;                          // 0,1,2
        const int e = j & 16383;
        const int n = e >> 7, k = e & 127;
        if (which == 0)      g_WdT[n * 128 + k] = __float2half_rn(Wm[(size_t)k * 128 + n]);
        else if (which == 1) g_WsT[n * 128 + k] = __float2half_rn(Wm[(size_t)(128 + k) * 128 + n]);
        else                 g_W2T[n * 128 + k] = __float2half_rn(W2[(size_t)k * 128 + n]);
    }
}

// ------------------------- gemm2: load z tile once, emit g_Ah = z@Wd, g_Bh = z@Ws (fp16) -------------------------
// smem (words): As [128][PA2F] (8704) + B0 (4608) + B1 (4608) = 17920 w = 71680 B -> 2 CTA/SM
#define GEMM2_SMEM (71680)

__global__ __launch_bounds__(256, 2) void gemm2_kernel(const float* __restrict__ z, int M)
{
    extern __shared__ uint32_t sm[];
    uint32_t* As = sm;                       // [128][PA2F] full K=128 (half2)
    uint32_t* Bbuf[2] = { sm + 128 * PA2F, sm + 128 * PA2F + 128 * PB2 };
    const uint32_t bAddr[2] = { smem_u32(Bbuf[0]), smem_u32(Bbuf[1]) };

    const int tid  = threadIdx.x;
    const int wid  = tid >> 5;
    const int lane = tid & 31;
    const int g    = lane >> 2;
    const int tg   = lane & 3;
    const int wm   = (wid & 3) << 5;
    const int wn   = (wid >> 2) << 6;
    const int rowBase = blockIdx.x * 128;

    // kick off B pipeline: step0 = (WdT, kw=0)
    cp_fill_B(bAddr[0], g_WdT, 0, 128, tid);
    CP_COMMIT();

    // load full A tile (128 x 128) as fp16 (overlaps the cp.async above)
#pragma unroll
    for (int it = 0; it < 16; it++) {
        const int i = it * 256 + tid;
        const int row = i >> 5;
        const int c4  = (i & 31) << 2;
        const int gr = rowBase + row;
        float4 v = make_float4(0.f, 0.f, 0.f, 0.f);
        if (gr < M) v = *(const float4*)(z + (size_t)gr * HID + c4);
        uint2 t;
        t.x = f2h2(v.x, v.y);
        t.y = f2h2(v.z, v.w);
        *(uint2*)(As + row * PA2F + (c4 >> 1)) = t;
    }

    // step table: 0:(WdT,0) 1:(WdT,64) 2:(WsT,0) 3:(WsT,64)
    int cur = 0;
    for (int w = 0; w < 2; w++) {
        float acc[2][8][4];
#pragma unroll
        for (int mt = 0; mt < 2; mt++)
#pragma unroll
            for (int nt = 0; nt < 8; nt++)
#pragma unroll
                for (int i = 0; i < 4; i++) acc[mt][nt][i] = 0.f;

        for (int chunk = 0; chunk < 2; chunk++) {
            const int step = w * 2 + chunk;
            if (step < 3) {
                const __half* nWT = (step == 0) ? g_WdT : g_WsT;
                const int nkw = (step == 1) ? 0 : 64;
                cp_fill_B(bAddr[cur ^ 1], nWT, nkw, 128, tid);
                CP_COMMIT();
                CP_WAIT1();
            } else {
                CP_WAIT0();
            }
            __syncthreads();
            mma_chunk_f16(acc, As, PA2F, chunk * 32, Bbuf[cur], wm, wn, g, tg);
            __syncthreads();
            cur ^= 1;
        }

#pragma unroll
        for (int mt = 0; mt < 2; mt++) {
            const int r0 = rowBase + wm + mt * 16 + g;
            const int r1 = r0 + 8;
#pragma unroll
            for (int nt = 0; nt < 8; nt++) {
                const int cb = wn + nt * 8 + tg * 2;
                __half2* dst = w ? g_Bh : g_Ah;
                if (r0 < M) dst[(size_t)r0 * (HID/2) + (cb >> 1)] =
                    __floats2half2_rn(acc[mt][nt][0], acc[mt][nt][1]);
                if (r1 < M) dst[(size_t)r1 * (HID/2) + (cb >> 1)] =
                    __floats2half2_rn(acc[mt][nt][2], acc[mt][nt][3]);
            }
        }
    }
}

// ------------------------- fused MLP: hidden = relu([z|agg]@W1 + b1); out = hidden@W2 + b2 -------------------------
// smem (words): As1 [128][PA2C] @0 (4608), B0 @4608 (4608), B1 @9216 (4608), hid [128][PA2F] @13824 (8704)
//               total 22528 w = 90112 B -> 2 CTA/SM
#define FUSED_SMEM (90112)

__global__ __launch_bounds__(256, 2) void fused_mlp_kernel(
    const float* __restrict__ z, const float* __restrict__ b1,
    const float* __restrict__ b2, float* __restrict__ out, int M)
{
    extern __shared__ uint32_t sm[];
    uint32_t* As1 = sm;                      // [128][PA2C]
    uint32_t* Bbuf[2] = { sm + 4608, sm + 9216 };
    uint32_t* hid = sm + 13824;              // [128][PA2F]
    const uint32_t bAddr[2] = { smem_u32(Bbuf[0]), smem_u32(Bbuf[1]) };

    const int tid  = threadIdx.x;
    const int wid  = tid >> 5;
    const int lane = tid & 31;
    const int g    = lane >> 2;
    const int tg   = lane & 3;
    const int wm   = (wid & 3) << 5;
    const int wn   = (wid >> 2) << 6;
    const int rowBase = blockIdx.x * 128;

    // kick off B pipeline: step0 = (W1T, kw=0)
    cp_fill_B(bAddr[0], g_W1T, 0, 256, tid);
    CP_COMMIT();

    float acc[2][8][4];
#pragma unroll
    for (int mt = 0; mt < 2; mt++)
#pragma unroll
        for (int nt = 0; nt < 8; nt++)
#pragma unroll
            for (int i = 0; i < 4; i++) acc[mt][nt][i] = 0.f;

    int cur = 0;
    // ---- stage 1: K=256 over [z | agg] with W1 ----
    for (int chunk = 0; chunk < 4; chunk++) {
        const int kloc = (chunk & 1) * 64;
        // A-chunk fill (sync; overlaps in-flight cp.async groups)
#pragma unroll
        for (int it = 0; it < 8; it++) {
            const int i = it * 256 + tid;
            const int row = i >> 4;
            const int c4  = (i & 15) << 2;
            const int gr = rowBase + row;
            uint2 t = make_uint2(0u, 0u);
            if (chunk < 2) {
                if (gr < M) {
                    const float4 v = *(const float4*)(z + (size_t)gr * HID + kloc + c4);
                    t.x = f2h2(v.x, v.y);
                    t.y = f2h2(v.z, v.w);
                }
            } else {
                if (gr < M)
                    t = *(const uint2*)(g_aggh + (size_t)gr * (HID/2) + ((kloc + c4) >> 1));
            }
            *(uint2*)(As1 + row * PA2C + (c4 >> 1)) = t;
        }
        // prefetch next step
        if (chunk < 3) {
            cp_fill_B(bAddr[cur ^ 1], g_W1T, (chunk + 1) * 64, 256, tid);
        } else {
            cp_fill_B(bAddr[cur ^ 1], g_W2T, 0, 128, tid);
        }
        CP_COMMIT();
        CP_WAIT1();
        __syncthreads();
        mma_chunk_f16(acc, As1, PA2C, 0, Bbuf[cur], wm, wn, g, tg);
        __syncthreads();
        cur ^= 1;
    }

    // ---- stage-1 epilogue: hid = fp16(relu(acc + b1)) ----
#pragma unroll
    for (int mt = 0; mt < 2; mt++) {
        const int lr0 = wm + mt * 16 + g;
        const int lr1 = lr0 + 8;
#pragma unroll
        for (int nt = 0; nt < 8; nt++) {
            const int cb = wn + nt * 8 + tg * 2;
            const float bb0 = b1[cb], bb1 = b1[cb + 1];
            hid[lr0 * PA2F + (cb >> 1)] =
                f2h2(fmaxf(acc[mt][nt][0] + bb0, 0.f), fmaxf(acc[mt][nt][1] + bb1, 0.f));
            hid[lr1 * PA2F + (cb >> 1)] =
                f2h2(fmaxf(acc[mt][nt][2] + bb0, 0.f), fmaxf(acc[mt][nt][3] + bb1, 0.f));
        }
    }
    __syncthreads();

    // ---- stage 2: out = hid @ W2 + b2 ----
#pragma unroll
    for (int mt = 0; mt < 2; mt++)
#pragma unroll
        for (int nt = 0; nt < 8; nt++)
#pragma unroll
            for (int i = 0; i < 4; i++) acc[mt][nt][i] = 0.f;

    for (int chunk = 0; chunk < 2; chunk++) {
        if (chunk == 0) {
            cp_fill_B(bAddr[cur ^ 1], g_W2T, 64, 128, tid);
            CP_COMMIT();
            CP_WAIT1();
        } else {
            CP_WAIT0();
        }
        __syncthreads();
        mma_chunk_f16(acc, hid, PA2F, chunk * 32, Bbuf[cur], wm, wn, g, tg);
        __syncthreads();
        cur ^= 1;
    }

#pragma unroll
    for (int mt = 0; mt < 2; mt++) {
        const int r0 = rowBase + wm + mt * 16 + g;
        const int r1 = r0 + 8;
#pragma unroll
        for (int nt = 0; nt < 8; nt++) {
            const int cb = wn + nt * 8 + tg * 2;
            const float bb0 = b2[cb], bb1 = b2[cb + 1];
            if (r0 < M) *(float2*)(out + (size_t)r0 * HID + cb) =
                make_float2(acc[mt][nt][0] + bb0, acc[mt][nt][1] + bb1);
            if (r1 < M) *(float2*)(out + (size_t)r1 * HID + cb) =
                make_float2(acc[mt][nt][2] + bb0, acc[mt][nt][3] + bb1);
        }
    }
}

// ------------------------- CSR build (3 kernels; zeroing folded into scan) -------------------------
__global__ void deg_kernel(const int* __restrict__ dst, int nE)
{
    int e = blockIdx.x * blockDim.x + threadIdx.x;
    if (e < nE) atomicAdd(&g_deg[dst[e]], 1);
}

__global__ __launch_bounds__(1024) void scan_kernel(int nNodes)
{
    __shared__ int warpPre[32];
    __shared__ int s_carry;
    const int tid = threadIdx.x;
    const int lane = tid & 31;
    const int wid = tid >> 5;
    if (tid == 0) s_carry = 0;
    __syncthreads();
    const int nChunks = (nNodes + 1023) >> 10;
    for (int c = 0; c < nChunks; c++) {
        const int i = (c << 10) + tid;
        const int v = (i < nNodes) ? g_deg[i] : 0;
        if (i < nNodes) g_deg[i] = 0;   // re-zero for next graph replay
        int incl = v;
#pragma unroll
        for (int o = 1; o < 32; o <<= 1) {
            int t = __shfl_up_sync(0xffffffffu, incl, o);
            if (lane >= o) incl += t;
        }
        if (lane == 31) warpPre[wid] = incl;
        __syncthreads();
        if (wid == 0) {
            int ws = warpPre[lane];
            int wincl = ws;
#pragma unroll
            for (int o = 1; o < 32; o <<= 1) {
                int t = __shfl_up_sync(0xffffffffu, wincl, o);
                if (lane >= o) wincl += t;
            }
            warpPre[lane] = wincl - ws;
        }
        __syncthreads();
        const int excl = s_carry + warpPre[wid] + incl - v;
        if (i < nNodes) { g_off[i] = excl; g_cur[i] = excl; }
        __syncthreads();
        if (tid == 1023) s_carry = excl + v;
        __syncthreads();
    }
    if (tid == 0) g_off[nNodes] = s_carry;
}

__global__ void scatter_kernel(const int* __restrict__ dst, int nE)
{
    int e = blockIdx.x * blockDim.x + threadIdx.x;
    if (e < nE) {
        int p = atomicAdd(&g_cur[dst[e]], 1);
        g_csr[p] = e;
    }
}

// ------------------------- per-node gather-max (fp16 rows, edge loop unrolled 2x) -------------------------
__global__ __launch_bounds__(256) void agg_kernel(
    const int* __restrict__ src, const float* __restrict__ ew,
    const float* __restrict__ Wm, const float* __restrict__ bm,
    int nNodes)
{
    const int warpId = (blockIdx.x * blockDim.x + threadIdx.x) >> 5;
    const int lane = threadIdx.x & 31;
    if (warpId >= nNodes) return;
    const int n = warpId;
    const float4 ww4 = *(const float4*)(Wm + 256 * HID + lane * 4);
    const int s0 = g_off[n], s1 = g_off[n + 1];
    float4 m = make_float4(-FLT_MAX, -FLT_MAX, -FLT_MAX, -FLT_MAX);
    for (int base = s0; base < s1; base += 32) {
        const int idx = base + lane;
        int sv = 0; float wv = 0.f;
        if (idx < s1) {
            const int e = g_csr[idx];
            sv = src[e];
            wv = ew[e];
        }
        const int cnt = min(32, s1 - base);
        int j = 0;
        for (; j + 1 < cnt; j += 2) {
            const int   sj0 = __shfl_sync(0xffffffffu, sv, j);
            const float wj0 = __shfl_sync(0xffffffffu, wv, j);
            const int   sj1 = __shfl_sync(0xffffffffu, sv, j + 1);
            const float wj1 = __shfl_sync(0xffffffffu, wv, j + 1);
            const uint2 h0 = *(const uint2*)(g_Bh + (size_t)sj0 * (HID/2) + lane * 2);
            const uint2 h1 = *(const uint2*)(g_Bh + (size_t)sj1 * (HID/2) + lane * 2);
            const float2 b0a = __half22float2(*(const __half2*)&h0.x);
            const float2 b0b = __half22float2(*(const __half2*)&h0.y);
            const float2 b1a = __half22float2(*(const __half2*)&h1.x);
            const float2 b1b = __half22float2(*(const __half2*)&h1.y);
            m.x = fmaxf(m.x, fmaf(wj0, ww4.x, b0a.x));
            m.y = fmaxf(m.y, fmaf(wj0, ww4.y, b0a.y));
            m.z = fmaxf(m.z, fmaf(wj0, ww4.z, b0b.x));
            m.w = fmaxf(m.w, fmaf(wj0, ww4.w, b0b.y));
            m.x = fmaxf(m.x, fmaf(wj1, ww4.x, b1a.x));
            m.y = fmaxf(m.y, fmaf(wj1, ww4.y, b1a.y));
            m.z = fmaxf(m.z, fmaf(wj1, ww4.z, b1b.x));
            m.w = fmaxf(m.w, fmaf(wj1, ww4.w, b1b.y));
        }
        if (j < cnt) {
            const int   sj = __shfl_sync(0xffffffffu, sv, j);
            const float wj = __shfl_sync(0xffffffffu, wv, j);
            const uint2 h0 = *(const uint2*)(g_Bh + (size_t)sj * (HID/2) + lane * 2);
            const float2 b0a = __half22float2(*(const __half2*)&h0.x);
            const float2 b0b = __half22float2(*(const __half2*)&h0.y);
            m.x = fmaxf(m.x, fmaf(wj, ww4.x, b0a.x));
            m.y = fmaxf(m.y, fmaf(wj, ww4.y, b0a.y));
            m.z = fmaxf(m.z, fmaf(wj, ww4.z, b0b.x));
            m.w = fmaxf(m.w, fmaf(wj, ww4.w, b0b.y));
        }
    }
    uint2 o;
    if (s1 > s0) {
        const uint2 a2 = *(const uint2*)(g_Ah + (size_t)n * (HID/2) + lane * 2);
        const float2 aa = __half22float2(*(const __half2*)&a2.x);
        const float2 ab = __half22float2(*(const __half2*)&a2.y);
        const float4 bm4 = *(const float4*)(bm + lane * 4);
        const __half2 o01 = __floats2half2_rn(aa.x + bm4.x + m.x, aa.y + bm4.y + m.y);
        const __half2 o23 = __floats2half2_rn(ab.x + bm4.z + m.z, ab.y + bm4.w + m.w);
        o.x = *(const uint32_t*)&o01;
        o.y = *(const uint32_t*)&o23;
    } else {
        o.x = 0u; o.y = 0u;
    }
    *(uint2*)(g_aggh + (size_t)n * (HID/2) + lane * 2) = o;
}

// ------------------------- launch -------------------------
extern "C" void kernel_launch(void* const* d_in, const int* in_sizes, int n_in,
                              void* d_out, int out_size)
{
    const float* z   = (const float*)d_in[0];
    const float* ew  = (const float*)d_in[1];
    const int*   esrc= (const int*)d_in[2];
    const int*   edst= (const int*)d_in[3];
    const float* Wm  = (const float*)d_in[4];
    const float* bm  = (const float*)d_in[5];
    const float* W1  = (const float*)d_in[6];
    const float* b1  = (const float*)d_in[7];
    const float* W2  = (const float*)d_in[8];
    const float* b2  = (const float*)d_in[9];
    float* out = (float*)d_out;

    const int nNodes = in_sizes[0] / HID;
    const int nEdges = in_sizes[1];

    cudaFuncSetAttribute(gemm2_kernel, cudaFuncAttributeMaxDynamicSharedMemorySize, GEMM2_SMEM);
    cudaFuncSetAttribute(fused_mlp_kernel, cudaFuncAttributeMaxDynamicSharedMemorySize, FUSED_SMEM);

    // lazily-created side stream + fork/join events (host-side objects, no device mem)
    static cudaStream_t s_side = nullptr;
    static cudaEvent_t  s_evFork = nullptr, s_evCsr = nullptr;
    if (!s_side) {
        cudaStreamCreateWithFlags(&s_side, cudaStreamNonBlocking);
        cudaEventCreateWithFlags(&s_evFork, cudaEventDisableTiming);
        cudaEventCreateWithFlags(&s_evCsr, cudaEventDisableTiming);
    }

    const int gemmGrid = (nNodes + 127) / 128;
    const int edgeGrid = (nEdges + 255) / 256;
    const int aggGrid  = (nNodes + 7) / 8;

    // fork: CSR build (edge-only inputs) runs concurrently with weight prep + gemm2
    cudaEventRecord(s_evFork, 0);
    cudaStreamWaitEvent(s_side, s_evFork, 0);

    // side stream: CSR build (g_deg zeroed by static init / prior scan)
    deg_kernel<<<edgeGrid, 256, 0, s_side>>>(edst, nEdges);
    scan_kernel<<<1, 1024, 0, s_side>>>(nNodes);
    scatter_kernel<<<edgeGrid, 256, 0, s_side>>>(edst, nEdges);
    cudaEventRecord(s_evCsr, s_side);

    // main stream: prep weights (fp16 transpose), then dual projection
    prep_weights<<<320, 256>>>(Wm, W1, W2);
    gemm2_kernel<<<gemmGrid, 256, GEMM2_SMEM>>>(z, nNodes);

    // join: agg needs both CSR and g_Ah/g_Bh
    cudaStreamWaitEvent(0, s_evCsr, 0);

    // segment max (gather form, fp16 rows)
    agg_kernel<<<aggGrid, 256>>>(esrc, ew, Wm, bm, nNodes);

    // fused: hidden = relu([z|agg]@W1 + b1); out = hidden@W2 + b2
    fused_mlp_kernel<<<gemmGrid, 256, FUSED_SMEM>>>(z, b1, b2, out, nNodes);
}

// round 17
// speedup vs baseline: 1.3891x; 1.0561x over previous
#include <cuda_runtime.h>
#include <cuda_fp16.h>
#include <math.h>
#include <float.h>
#include <stdint.h>

#define HID 128
#define MAX_NODES 50000
#define MAX_EDGES 800000

// ------------------------- scratch (static, no allocs) -------------------------
__device__ float   g_A[MAX_NODES * HID];       // z @ Wd (fp32)
__device__ __half2 g_Bh[MAX_NODES * (HID/2)];  // z @ Ws (fp16 storage)
__device__ __half2 g_aggh[MAX_NODES * (HID/2)];// agg result (fp16 storage)
__device__ int     g_deg[MAX_NODES];
__device__ int     g_off[MAX_NODES + 1];
__device__ int     g_cur[MAX_NODES];
__device__ int     g_csr[MAX_EDGES];

// pre-transposed fp16 weights: [n][k] layout (B-tile ready, no per-tile transpose/convert)
__device__ __align__(16) __half g_WdT[128 * 128];
__device__ __align__(16) __half g_WsT[128 * 128];
__device__ __align__(16) __half g_W1T[128 * 256];
__device__ __align__(16) __half g_W2T[128 * 128];

// ------------------------- helpers (sm_80+ baseline PTX only) -------------------------
__device__ __forceinline__ uint32_t smem_u32(const void* p) {
    uint32_t a;
    asm("{ .reg .u64 t; cvta.to.shared.u64 t, %1; cvt.u32.u64 %0, t; }" : "=r"(a) : "l"(p));
    return a;
}

__device__ __forceinline__ void cp16(uint32_t dst, const void* src) {
    asm volatile("cp.async.cg.shared.global [%0], [%1], 16;" :: "r"(dst), "l"(src));
}
#define CP_COMMIT()  asm volatile("cp.async.commit_group;" ::: "memory")
#define CP_WAIT1()   asm volatile("cp.async.wait_group 1;" ::: "memory")
#define CP_WAIT0()   asm volatile("cp.async.wait_group 0;" ::: "memory")

__device__ __forceinline__ uint32_t f2h2(float a, float b) {
    const __half2 h = __floats2half2_rn(a, b);
    return *(const uint32_t*)&h;
}

__device__ __forceinline__ void mma_f16(float* c, const uint32_t* a, uint32_t b0, uint32_t b1) {
    asm volatile(
        "mma.sync.aligned.m16n8k16.row.col.f32.f16.f16.f32 "
        "{%0,%1,%2,%3}, {%4,%5,%6,%7}, {%8,%9}, {%0,%1,%2,%3};"
        : "+f"(c[0]), "+f"(c[1]), "+f"(c[2]), "+f"(c[3])
        : "r"(a[0]), "r"(a[1]), "r"(a[2]), "r"(a[3]), "r"(b0), "r"(b1));
}

// tiling: CTA = 256 thr = 8 warps (4M x 2N), tile 128(M) x 128(N)
// pitches in half2 (uint32) units; pitch=4*odd -> frag loads conflict-free
#define PA2C 36    // chunk-A pitch
#define PA2F 68    // full-A / hid pitch
#define PB2  36    // B pitch, [n][k] transposed

// ------------------------- compute core: 4 k16-steps over one 64-K chunk -------------------------
__device__ __forceinline__ void mma_chunk_f16(
    float acc[2][8][4], const uint32_t* __restrict__ Asm, int apitch2, int acol2,
    const uint32_t* __restrict__ Bsm, int wm, int wn, int g, int tg)
{
#pragma unroll
    for (int kk2 = 0; kk2 < 32; kk2 += 8) {   // 8 half2 = 16 K per step
        uint32_t a[2][4];
#pragma unroll
        for (int mt = 0; mt < 2; mt++) {
            const uint32_t* ap = Asm + (wm + mt * 16 + g) * apitch2 + acol2 + kk2 + tg;
            a[mt][0] = ap[0];
            a[mt][1] = ap[8 * apitch2];
            a[mt][2] = ap[4];
            a[mt][3] = ap[8 * apitch2 + 4];
        }
#pragma unroll
        for (int nt = 0; nt < 8; nt++) {
            const uint32_t* bp = Bsm + (wn + nt * 8 + g) * PB2 + kk2 + tg;
            const uint32_t b0 = bp[0];
            const uint32_t b1 = bp[4];
            mma_f16(acc[0][nt], a[0], b0, b1);
            mma_f16(acc[1][nt], a[1], b0, b1);
        }
    }
}

// async B fill: WT[n][kw..kw+64) fp16 -> Bs[n][k2] (row = 128B, 8x16B chunks)
__device__ __forceinline__ void cp_fill_B(
    uint32_t dstBase, const __half* __restrict__ WT, int kw, int kstride, int tid)
{
#pragma unroll
    for (int it = 0; it < 4; it++) {
        const int i = it * 256 + tid;     // 0..1023
        const int n = i >> 3;             // row 0..127
        const int c = i & 7;              // 16B chunk
        cp16(dstBase + n * (PB2 * 4) + c * 16, WT + (size_t)n * kstride + kw + c * 8);
    }
}

// ------------------------- weight prep: transpose + fp16 convert (flat, 1 elem/thread) -------------------------
__global__ void prep_weights(const float* __restrict__ Wm, const float* __restrict__ W1,
                             const float* __restrict__ W2)
{
    const int i = blockIdx.x * blockDim.x + threadIdx.x;   // 0 .. 81919
    if (i < 128 * 256) {                                    // W1T
        const int n = i >> 8, k = i & 255;
        g_W1T[n * 256 + k] = __float2half_rn(W1[(size_t)k * 128 + n]);
    } else {
        const int j = i - 128 * 256;                        // 0 .. 49151
        const int which = j >> 14;                          // 0,1,2
        const int e = j & 16383;
        const int n = e >> 7, k = e & 127;
        if (which == 0)      g_WdT[n * 128 + k] = __float2half_rn(Wm[(size_t)k * 128 + n]);
        else if (which == 1) g_WsT[n * 128 + k] = __float2half_rn(Wm[(size_t)(128 + k) * 128 + n]);
        else                 g_W2T[n * 128 + k] = __float2half_rn(W2[(size_t)k * 128 + n]);
    }
}

// ------------------------- gemm2: load z tile once, emit g_A = z@Wd (fp32), g_Bh = z@Ws (fp16) -------------------------
// smem (words): As [128][PA2F] (8704) + B0 (4608) + B1 (4608) = 17920 w = 71680 B -> 2 CTA/SM
#define GEMM2_SMEM (71680)

__global__ __launch_bounds__(256, 2) void gemm2_kernel(const float* __restrict__ z, int M)
{
    extern __shared__ uint32_t sm[];
    uint32_t* As = sm;                       // [128][PA2F] full K=128 (half2)
    uint32_t* Bbuf[2] = { sm + 128 * PA2F, sm + 128 * PA2F + 128 * PB2 };
    const uint32_t bAddr[2] = { smem_u32(Bbuf[0]), smem_u32(Bbuf[1]) };

    const int tid  = threadIdx.x;
    const int wid  = tid >> 5;
    const int lane = tid & 31;
    const int g    = lane >> 2;
    const int tg   = lane & 3;
    const int wm   = (wid & 3) << 5;
    const int wn   = (wid >> 2) << 6;
    const int rowBase = blockIdx.x * 128;

    // kick off B pipeline: step0 = (WdT, kw=0)
    cp_fill_B(bAddr[0], g_WdT, 0, 128, tid);
    CP_COMMIT();

    // load full A tile (128 x 128) as fp16 (overlaps the cp.async above)
#pragma unroll
    for (int it = 0; it < 16; it++) {
        const int i = it * 256 + tid;
        const int row = i >> 5;
        const int c4  = (i & 31) << 2;
        const int gr = rowBase + row;
        float4 v = make_float4(0.f, 0.f, 0.f, 0.f);
        if (gr < M) v = *(const float4*)(z + (size_t)gr * HID + c4);
        uint2 t;
        t.x = f2h2(v.x, v.y);
        t.y = f2h2(v.z, v.w);
        *(uint2*)(As + row * PA2F + (c4 >> 1)) = t;
    }

    // step table: 0:(WdT,0) 1:(WdT,64) 2:(WsT,0) 3:(WsT,64)
    int cur = 0;
    for (int w = 0; w < 2; w++) {
        float acc[2][8][4];
#pragma unroll
        for (int mt = 0; mt < 2; mt++)
#pragma unroll
            for (int nt = 0; nt < 8; nt++)
#pragma unroll
                for (int i = 0; i < 4; i++) acc[mt][nt][i] = 0.f;

        for (int chunk = 0; chunk < 2; chunk++) {
            const int step = w * 2 + chunk;
            if (step < 3) {
                const __half* nWT = (step == 0) ? g_WdT : g_WsT;
                const int nkw = (step == 1) ? 0 : 64;
                cp_fill_B(bAddr[cur ^ 1], nWT, nkw, 128, tid);
                CP_COMMIT();
                CP_WAIT1();
            } else {
                CP_WAIT0();
            }
            __syncthreads();
            mma_chunk_f16(acc, As, PA2F, chunk * 32, Bbuf[cur], wm, wn, g, tg);
            __syncthreads();
            cur ^= 1;
        }

#pragma unroll
        for (int mt = 0; mt < 2; mt++) {
            const int r0 = rowBase + wm + mt * 16 + g;
            const int r1 = r0 + 8;
#pragma unroll
            for (int nt = 0; nt < 8; nt++) {
                const int cb = wn + nt * 8 + tg * 2;
                if (w == 0) {
                    if (r0 < M) *(float2*)(g_A + (size_t)r0 * HID + cb) =
                        make_float2(acc[mt][nt][0], acc[mt][nt][1]);
                    if (r1 < M) *(float2*)(g_A + (size_t)r1 * HID + cb) =
                        make_float2(acc[mt][nt][2], acc[mt][nt][3]);
                } else {
                    if (r0 < M) g_Bh[(size_t)r0 * (HID/2) + (cb >> 1)] =
                        __floats2half2_rn(acc[mt][nt][0], acc[mt][nt][1]);
                    if (r1 < M) g_Bh[(size_t)r1 * (HID/2) + (cb >> 1)] =
                        __floats2half2_rn(acc[mt][nt][2], acc[mt][nt][3]);
                }
            }
        }
    }
}

// ------------------------- fused MLP: hidden = relu([z|agg]@W1 + b1); out = hidden@W2 + b2 -------------------------
// smem (words): As1 [128][PA2C] @0 (4608), B0 @4608 (4608), B1 @9216 (4608), hid [128][PA2F] @13824 (8704)
//               total 22528 w = 90112 B -> 2 CTA/SM
#define FUSED_SMEM (90112)

__global__ __launch_bounds__(256, 2) void fused_mlp_kernel(
    const float* __restrict__ z, const float* __restrict__ b1,
    const float* __restrict__ b2, float* __restrict__ out, int M)
{
    extern __shared__ uint32_t sm[];
    uint32_t* As1 = sm;                      // [128][PA2C]
    uint32_t* Bbuf[2] = { sm + 4608, sm + 9216 };
    uint32_t* hid = sm + 13824;              // [128][PA2F]
    const uint32_t bAddr[2] = { smem_u32(Bbuf[0]), smem_u32(Bbuf[1]) };

    const int tid  = threadIdx.x;
    const int wid  = tid >> 5;
    const int lane = tid & 31;
    const int g    = lane >> 2;
    const int tg   = lane & 3;
    const int wm   = (wid & 3) << 5;
    const int wn   = (wid >> 2) << 6;
    const int rowBase = blockIdx.x * 128;

    // kick off B pipeline: step0 = (W1T, kw=0)
    cp_fill_B(bAddr[0], g_W1T, 0, 256, tid);
    CP_COMMIT();

    float acc[2][8][4];
#pragma unroll
    for (int mt = 0; mt < 2; mt++)
#pragma unroll
        for (int nt = 0; nt < 8; nt++)
#pragma unroll
            for (int i = 0; i < 4; i++) acc[mt][nt][i] = 0.f;

    int cur = 0;
    // ---- stage 1: K=256 over [z | agg] with W1 ----
    for (int chunk = 0; chunk < 4; chunk++) {
        const int kloc = (chunk & 1) * 64;
        // A-chunk fill (sync; overlaps in-flight cp.async groups)
#pragma unroll
        for (int it = 0; it < 8; it++) {
            const int i = it * 256 + tid;
            const int row = i >> 4;
            const int c4  = (i & 15) << 2;
            const int gr = rowBase + row;
            uint2 t = make_uint2(0u, 0u);
            if (chunk < 2) {
                if (gr < M) {
                    const float4 v = *(const float4*)(z + (size_t)gr * HID + kloc + c4);
                    t.x = f2h2(v.x, v.y);
                    t.y = f2h2(v.z, v.w);
                }
            } else {
                if (gr < M)
                    t = *(const uint2*)(g_aggh + (size_t)gr * (HID/2) + ((kloc + c4) >> 1));
            }
            *(uint2*)(As1 + row * PA2C + (c4 >> 1)) = t;
        }
        // prefetch next step
        if (chunk < 3) {
            cp_fill_B(bAddr[cur ^ 1], g_W1T, (chunk + 1) * 64, 256, tid);
        } else {
            cp_fill_B(bAddr[cur ^ 1], g_W2T, 0, 128, tid);
        }
        CP_COMMIT();
        CP_WAIT1();
        __syncthreads();
        mma_chunk_f16(acc, As1, PA2C, 0, Bbuf[cur], wm, wn, g, tg);
        __syncthreads();
        cur ^= 1;
    }

    // ---- stage-1 epilogue: hid = fp16(relu(acc + b1)) ----
#pragma unroll
    for (int mt = 0; mt < 2; mt++) {
        const int lr0 = wm + mt * 16 + g;
        const int lr1 = lr0 + 8;
#pragma unroll
        for (int nt = 0; nt < 8; nt++) {
            const int cb = wn + nt * 8 + tg * 2;
            const float bb0 = b1[cb], bb1 = b1[cb + 1];
            hid[lr0 * PA2F + (cb >> 1)] =
                f2h2(fmaxf(acc[mt][nt][0] + bb0, 0.f), fmaxf(acc[mt][nt][1] + bb1, 0.f));
            hid[lr1 * PA2F + (cb >> 1)] =
                f2h2(fmaxf(acc[mt][nt][2] + bb0, 0.f), fmaxf(acc[mt][nt][3] + bb1, 0.f));
        }
    }
    __syncthreads();

    // ---- stage 2: out = hid @ W2 + b2 ----
#pragma unroll
    for (int mt = 0; mt < 2; mt++)
#pragma unroll
        for (int nt = 0; nt < 8; nt++)
#pragma unroll
            for (int i = 0; i < 4; i++) acc[mt][nt][i] = 0.f;

    for (int chunk = 0; chunk < 2; chunk++) {
        if (chunk == 0) {
            cp_fill_B(bAddr[cur ^ 1], g_W2T, 64, 128, tid);
            CP_COMMIT();
            CP_WAIT1();
        } else {
            CP_WAIT0();
        }
        __syncthreads();
        mma_chunk_f16(acc, hid, PA2F, chunk * 32, Bbuf[cur], wm, wn, g, tg);
        __syncthreads();
        cur ^= 1;
    }

#pragma unroll
    for (int mt = 0; mt < 2; mt++) {
        const int r0 = rowBase + wm + mt * 16 + g;
        const int r1 = r0 + 8;
#pragma unroll
        for (int nt = 0; nt < 8; nt++) {
            const int cb = wn + nt * 8 + tg * 2;
            const float bb0 = b2[cb], bb1 = b2[cb + 1];
            if (r0 < M) *(float2*)(out + (size_t)r0 * HID + cb) =
                make_float2(acc[mt][nt][0] + bb0, acc[mt][nt][1] + bb1);
            if (r1 < M) *(float2*)(out + (size_t)r1 * HID + cb) =
                make_float2(acc[mt][nt][2] + bb0, acc[mt][nt][3] + bb1);
        }
    }
}

// ------------------------- CSR build -------------------------
__global__ void zero_deg_kernel(int nNodes)
{
    int i = blockIdx.x * blockDim.x + threadIdx.x;
    if (i < nNodes) g_deg[i] = 0;
}

__global__ void deg_kernel(const int* __restrict__ dst, int nE)
{
    int e = blockIdx.x * blockDim.x + threadIdx.x;
    if (e < nE) atomicAdd(&g_deg[dst[e]], 1);
}

__global__ __launch_bounds__(1024) void scan_kernel(int nNodes)
{
    __shared__ int warpPre[32];
    __shared__ int s_carry;
    const int tid = threadIdx.x;
    const int lane = tid & 31;
    const int wid = tid >> 5;
    if (tid == 0) s_carry = 0;
    __syncthreads();
    const int nChunks = (nNodes + 1023) >> 10;
    for (int c = 0; c < nChunks; c++) {
        const int i = (c << 10) + tid;
        const int v = (i < nNodes) ? g_deg[i] : 0;
        int incl = v;
#pragma unroll
        for (int o = 1; o < 32; o <<= 1) {
            int t = __shfl_up_sync(0xffffffffu, incl, o);
            if (lane >= o) incl += t;
        }
        if (lane == 31) warpPre[wid] = incl;
        __syncthreads();
        if (wid == 0) {
            int ws = warpPre[lane];
            int wincl = ws;
#pragma unroll
            for (int o = 1; o < 32; o <<= 1) {
                int t = __shfl_up_sync(0xffffffffu, wincl, o);
                if (lane >= o) wincl += t;
            }
            warpPre[lane] = wincl - ws;
        }
        __syncthreads();
        const int excl = s_carry + warpPre[wid] + incl - v;
        if (i < nNodes) { g_off[i] = excl; g_cur[i] = excl; }
        __syncthreads();
        if (tid == 1023) s_carry = excl + v;
        __syncthreads();
    }
    if (tid == 0) g_off[nNodes] = s_carry;
}

__global__ void scatter_kernel(const int* __restrict__ dst, int nE)
{
    int e = blockIdx.x * blockDim.x + threadIdx.x;
    if (e < nE) {
        int p = atomicAdd(&g_cur[dst[e]], 1);
        g_csr[p] = e;
    }
}

// ------------------------- per-node gather-max (fp16 g_B rows, edge loop unrolled 4x) -------------------------
__global__ __launch_bounds__(256) void agg_kernel(
    const int* __restrict__ src, const float* __restrict__ ew,
    const float* __restrict__ Wm, const float* __restrict__ bm,
    int nNodes)
{
    const int warpId = (blockIdx.x * blockDim.x + threadIdx.x) >> 5;
    const int lane = threadIdx.x & 31;
    if (warpId >= nNodes) return;
    const int n = warpId;
    const float4 ww4 = *(const float4*)(Wm + 256 * HID + lane * 4);
    const int s0 = g_off[n], s1 = g_off[n + 1];
    float4 m = make_float4(-FLT_MAX, -FLT_MAX, -FLT_MAX, -FLT_MAX);
    for (int base = s0; base < s1; base += 32) {
        const int idx = base + lane;
        int sv = 0; float wv = 0.f;
        if (idx < s1) {
            const int e = g_csr[idx];
            sv = src[e];
            wv = ew[e];
        }
        const int cnt = min(32, s1 - base);
        int j = 0;
        for (; j + 3 < cnt; j += 4) {
            const int   sj0 = __shfl_sync(0xffffffffu, sv, j);
            const float wj0 = __shfl_sync(0xffffffffu, wv, j);
            const int   sj1 = __shfl_sync(0xffffffffu, sv, j + 1);
            const float wj1 = __shfl_sync(0xffffffffu, wv, j + 1);
            const int   sj2 = __shfl_sync(0xffffffffu, sv, j + 2);
            const float wj2 = __shfl_sync(0xffffffffu, wv, j + 2);
            const int   sj3 = __shfl_sync(0xffffffffu, sv, j + 3);
            const float wj3 = __shfl_sync(0xffffffffu, wv, j + 3);
            const uint2 h0 = *(const uint2*)(g_Bh + (size_t)sj0 * (HID/2) + lane * 2);
            const uint2 h1 = *(const uint2*)(g_Bh + (size_t)sj1 * (HID/2) + lane * 2);
            const uint2 h2 = *(const uint2*)(g_Bh + (size_t)sj2 * (HID/2) + lane * 2);
            const uint2 h3 = *(const uint2*)(g_Bh + (size_t)sj3 * (HID/2) + lane * 2);
            const float2 b0a = __half22float2(*(const __half2*)&h0.x);
            const float2 b0b = __half22float2(*(const __half2*)&h0.y);
            const float2 b1a = __half22float2(*(const __half2*)&h1.x);
            const float2 b1b = __half22float2(*(const __half2*)&h1.y);
            const float2 b2a = __half22float2(*(const __half2*)&h2.x);
            const float2 b2b = __half22float2(*(const __half2*)&h2.y);
            const float2 b3a = __half22float2(*(const __half2*)&h3.x);
            const float2 b3b = __half22float2(*(const __half2*)&h3.y);
            m.x = fmaxf(m.x, fmaf(wj0, ww4.x, b0a.x));
            m.y = fmaxf(m.y, fmaf(wj0, ww4.y, b0a.y));
            m.z = fmaxf(m.z, fmaf(wj0, ww4.z, b0b.x));
            m.w = fmaxf(m.w, fmaf(wj0, ww4.w, b0b.y));
            m.x = fmaxf(m.x, fmaf(wj1, ww4.x, b1a.x));
            m.y = fmaxf(m.y, fmaf(wj1, ww4.y, b1a.y));
            m.z = fmaxf(m.z, fmaf(wj1, ww4.z, b1b.x));
            m.w = fmaxf(m.w, fmaf(wj1, ww4.w, b1b.y));
            m.x = fmaxf(m.x, fmaf(wj2, ww4.x, b2a.x));
            m.y = fmaxf(m.y, fmaf(wj2, ww4.y, b2a.y));
            m.z = fmaxf(m.z, fmaf(wj2, ww4.z, b2b.x));
            m.w = fmaxf(m.w, fmaf(wj2, ww4.w, b2b.y));
            m.x = fmaxf(m.x, fmaf(wj3, ww4.x, b3a.x));
            m.y = fmaxf(m.y, fmaf(wj3, ww4.y, b3a.y));
            m.z = fmaxf(m.z, fmaf(wj3, ww4.z, b3b.x));
            m.w = fmaxf(m.w, fmaf(wj3, ww4.w, b3b.y));
        }
        for (; j < cnt; j++) {
            const int   sj = __shfl_sync(0xffffffffu, sv, j);
            const float wj = __shfl_sync(0xffffffffu, wv, j);
            const uint2 h0 = *(const uint2*)(g_Bh + (size_t)sj * (HID/2) + lane * 2);
            const float2 b0a = __half22float2(*(const __half2*)&h0.x);
            const float2 b0b = __half22float2(*(const __half2*)&h0.y);
            m.x = fmaxf(m.x, fmaf(wj, ww4.x, b0a.x));
            m.y = fmaxf(m.y, fmaf(wj, ww4.y, b0a.y));
            m.z = fmaxf(m.z, fmaf(wj, ww4.z, b0b.x));
            m.w = fmaxf(m.w, fmaf(wj, ww4.w, b0b.y));
        }
    }
    uint2 o;
    if (s1 > s0) {
        const float4 a4 = *(const float4*)(g_A + (size_t)n * HID + lane * 4);
        const float4 bm4 = *(const float4*)(bm + lane * 4);
        const __half2 o01 = __floats2half2_rn(a4.x + bm4.x + m.x, a4.y + bm4.y + m.y);
        const __half2 o23 = __floats2half2_rn(a4.z + bm4.z + m.z, a4.w + bm4.w + m.w);
        o.x = *(const uint32_t*)&o01;
        o.y = *(const uint32_t*)&o23;
    } else {
        o.x = 0u; o.y = 0u;
    }
    *(uint2*)(g_aggh + (size_t)n * (HID/2) + lane * 2) = o;
}

// ------------------------- launch -------------------------
extern "C" void kernel_launch(void* const* d_in, const int* in_sizes, int n_in,
                              void* d_out, int out_size)
{
    const float* z   = (const float*)d_in[0];
    const float* ew  = (const float*)d_in[1];
    const int*   esrc= (const int*)d_in[2];
    const int*   edst= (const int*)d_in[3];
    const float* Wm  = (const float*)d_in[4];
    const float* bm  = (const float*)d_in[5];
    const float* W1  = (const float*)d_in[6];
    const float* b1  = (const float*)d_in[7];
    const float* W2  = (const float*)d_in[8];
    const float* b2  = (const float*)d_in[9];
    float* out = (float*)d_out;

    const int nNodes = in_sizes[0] / HID;
    const int nEdges = in_sizes[1];

    cudaFuncSetAttribute(gemm2_kernel, cudaFuncAttributeMaxDynamicSharedMemorySize, GEMM2_SMEM);
    cudaFuncSetAttribute(fused_mlp_kernel, cudaFuncAttributeMaxDynamicSharedMemorySize, FUSED_SMEM);

    // lazily-created side stream + fork/join events (host-side objects, no device mem)
    static cudaStream_t s_side = nullptr;
    static cudaEvent_t  s_evFork = nullptr, s_evCsr = nullptr;
    if (!s_side) {
        cudaStreamCreateWithFlags(&s_side, cudaStreamNonBlocking);
        cudaEventCreateWithFlags(&s_evFork, cudaEventDisableTiming);
        cudaEventCreateWithFlags(&s_evCsr, cudaEventDisableTiming);
    }

    const int gemmGrid = (nNodes + 127) / 128;
    const int edgeGrid = (nEdges + 255) / 256;
    const int nodeGrid = (nNodes + 255) / 256;
    const int aggGrid  = (nNodes + 7) / 8;

    // fork: CSR build (edge-only inputs) runs concurrently with weight prep + gemm2
    cudaEventRecord(s_evFork, 0);
    cudaStreamWaitEvent(s_side, s_evFork, 0);

    // side stream: CSR build
    zero_deg_kernel<<<nodeGrid, 256, 0, s_side>>>(nNodes);
    deg_kernel<<<edgeGrid, 256, 0, s_side>>>(edst, nEdges);
    scan_kernel<<<1, 1024, 0, s_side>>>(nNodes);
    scatter_kernel<<<edgeGrid, 256, 0, s_side>>>(edst, nEdges);
    cudaEventRecord(s_evCsr, s_side);

    // main stream: prep weights (fp16 transpose), then dual projection
    prep_weights<<<320, 256>>>(Wm, W1, W2);
    gemm2_kernel<<<gemmGrid, 256, GEMM2_SMEM>>>(z, nNodes);

    // join: agg needs both CSR and g_A/g_Bh
    cudaStreamWaitEvent(0, s_evCsr, 0);

    // segment max (gather form, fp16 rows)
    agg_kernel<<<aggGrid, 256>>>(esrc, ew, Wm, bm, nNodes);

    // fused: hidden = relu([z|agg]@W1 + b1); out = hidden@W2 + b2
    fused_mlp_kernel<<<gemmGrid, 256, FUSED_SMEM>>>(z, b1, b2, out, nNodes);
}